// round 4
// baseline (speedup 1.0000x reference)
#include <cuda_runtime.h>
#include <cuda_bf16.h>
#include <cstdint>

// Problem sizes (fixed by the reference)
#define BATCH 4
#define SEQ   2048
#define DIM   1024
#define MTOT  (BATCH * SEQ)   // 8192

// ---------------------------------------------------------------------------
// Scratch (static __device__ arrays — no allocation allowed)
// Q/K/V stored as split bf16 (hi + lo) so downstream GEMMs read tensor-core-
// ready operands. Scores/probs in fp32.
// ---------------------------------------------------------------------------
__device__ __nv_bfloat16 g_Qh[(size_t)MTOT * DIM];
__device__ __nv_bfloat16 g_Ql[(size_t)MTOT * DIM];
__device__ __nv_bfloat16 g_Kh[(size_t)MTOT * DIM];
__device__ __nv_bfloat16 g_Kl[(size_t)MTOT * DIM];
__device__ __nv_bfloat16 g_Vh[(size_t)MTOT * DIM];
__device__ __nv_bfloat16 g_Vl[(size_t)MTOT * DIM];
__device__ float         g_Sc[(size_t)BATCH * SEQ * SEQ];   // 64 MB

// ---------------------------------------------------------------------------
// PTX helpers
// ---------------------------------------------------------------------------
__device__ __forceinline__ uint32_t smem_u32(const void* p) {
    return (uint32_t)__cvta_generic_to_shared(p);
}

__device__ __forceinline__ void ldsm4(uint32_t addr, uint32_t& r0, uint32_t& r1,
                                      uint32_t& r2, uint32_t& r3) {
    asm volatile("ldmatrix.sync.aligned.m8n8.x4.shared.b16 {%0,%1,%2,%3},[%4];"
                 : "=r"(r0), "=r"(r1), "=r"(r2), "=r"(r3) : "r"(addr));
}

__device__ __forceinline__ void ldsm4t(uint32_t addr, uint32_t& r0, uint32_t& r1,
                                       uint32_t& r2, uint32_t& r3) {
    asm volatile("ldmatrix.sync.aligned.m8n8.x4.trans.shared.b16 {%0,%1,%2,%3},[%4];"
                 : "=r"(r0), "=r"(r1), "=r"(r2), "=r"(r3) : "r"(addr));
}

__device__ __forceinline__ void mma16816(float* c, const uint32_t* a, const uint32_t* b) {
    asm volatile(
        "mma.sync.aligned.m16n8k16.row.col.f32.bf16.bf16.f32 "
        "{%0,%1,%2,%3},{%4,%5,%6,%7},{%8,%9},{%0,%1,%2,%3};"
        : "+f"(c[0]), "+f"(c[1]), "+f"(c[2]), "+f"(c[3])
        : "r"(a[0]), "r"(a[1]), "r"(a[2]), "r"(a[3]), "r"(b[0]), "r"(b[1]));
}

__device__ __forceinline__ void split2(float x, __nv_bfloat16& h, __nv_bfloat16& l) {
    h = __float2bfloat16(x);                            // rn
    l = __float2bfloat16(x - __bfloat162float(h));      // residual, exact subtract
}

// ---------------------------------------------------------------------------
// Shared-memory tile layouts:
//   A tiles:   [128][40] bf16  (BK=32 + pad 8; 80B row stride, 16B aligned,
//                               ldmatrix bank-conflict free)
//   B (n,k):   [128][40] bf16  (scores kernel: K rows are k-contiguous)
//   B (k,n):   [32][136] bf16  (weights / V: n-contiguous rows, trans ldmatrix)
// ---------------------------------------------------------------------------
#define LDA  40
#define LDBT 136

// Core 128x128x32 split-bf16 MMA step. 8 warps as 2(m) x 4(n); each warp owns
// 64x32 of C: 4 m16 tiles x 4 n8 tiles, 3 split combos -> 48 mma per BK=32.
template <int LDB, bool BTRANS>
__device__ __forceinline__ void mma_tile(const __nv_bfloat16* Ah, const __nv_bfloat16* Al,
                                         const __nv_bfloat16* Bh, const __nv_bfloat16* Bl,
                                         float acc[4][4][4]) {
    const int lane = threadIdx.x & 31;
    const int warp = threadIdx.x >> 5;
    const int wm = (warp >> 2) * 64;
    const int wn = (warp & 3) * 32;

#pragma unroll
    for (int ks = 0; ks < 32; ks += 16) {
        uint32_t ah[4][4], al[4][4];
#pragma unroll
        for (int mt = 0; mt < 4; mt++) {
            const int row = wm + mt * 16 + (lane & 15);
            const int col = ks + ((lane >> 4) << 3);
            ldsm4(smem_u32(Ah + row * LDA + col), ah[mt][0], ah[mt][1], ah[mt][2], ah[mt][3]);
            ldsm4(smem_u32(Al + row * LDA + col), al[mt][0], al[mt][1], al[mt][2], al[mt][3]);
        }
        uint32_t bh[4][2], bl[4][2];
#pragma unroll
        for (int np = 0; np < 2; np++) {
            const int nb = wn + np * 16;
            uint32_t r0, r1, r2, r3;
            if (BTRANS) {
                const int grp  = lane >> 3;
                const int krow = ks + ((grp & 1) << 3) + (lane & 7);
                const int ncol = nb + ((grp & 2) << 2);
                ldsm4t(smem_u32(Bh + krow * LDB + ncol), r0, r1, r2, r3);
                bh[2 * np][0] = r0; bh[2 * np][1] = r1;
                bh[2 * np + 1][0] = r2; bh[2 * np + 1][1] = r3;
                ldsm4t(smem_u32(Bl + krow * LDB + ncol), r0, r1, r2, r3);
                bl[2 * np][0] = r0; bl[2 * np][1] = r1;
                bl[2 * np + 1][0] = r2; bl[2 * np + 1][1] = r3;
            } else {
                const int grp  = lane >> 3;
                const int nrow = nb + ((grp & 2) << 2) + (lane & 7);
                const int kcol = ks + ((grp & 1) << 3);
                ldsm4(smem_u32(Bh + nrow * LDB + kcol), r0, r1, r2, r3);
                bh[2 * np][0] = r0; bh[2 * np][1] = r1;
                bh[2 * np + 1][0] = r2; bh[2 * np + 1][1] = r3;
                ldsm4(smem_u32(Bl + nrow * LDB + kcol), r0, r1, r2, r3);
                bl[2 * np][0] = r0; bl[2 * np][1] = r1;
                bl[2 * np + 1][0] = r2; bl[2 * np + 1][1] = r3;
            }
        }
#pragma unroll
        for (int mt = 0; mt < 4; mt++)
#pragma unroll
            for (int nt = 0; nt < 4; nt++) {
                mma16816(acc[mt][nt], ah[mt], bh[nt]);   // hi*hi
                mma16816(acc[mt][nt], ah[mt], bl[nt]);   // hi*lo
                mma16816(acc[mt][nt], al[mt], bh[nt]);   // lo*hi
            }
    }
}

// ---- tile loaders ---------------------------------------------------------

// fp32 [128][32] tile -> split hi/lo into [128][40]
__device__ __forceinline__ void loadA_f32(const float* g, int ld,
                                          __nv_bfloat16* Ah, __nv_bfloat16* Al) {
    const int tid = threadIdx.x;
#pragma unroll
    for (int i = 0; i < 4; i++) {
        const int idx = tid + i * 256;          // 1024 float4 total
        const int r = idx >> 3;
        const int c = (idx & 7) * 4;
        float4 v = *reinterpret_cast<const float4*>(g + (size_t)r * ld + c);
        __nv_bfloat16* ph = Ah + r * LDA + c;
        __nv_bfloat16* pl = Al + r * LDA + c;
        split2(v.x, ph[0], pl[0]);
        split2(v.y, ph[1], pl[1]);
        split2(v.z, ph[2], pl[2]);
        split2(v.w, ph[3], pl[3]);
    }
}

// fp32 [32][128] weight tile -> split hi/lo into [32][136]
__device__ __forceinline__ void loadB_f32(const float* g, int ld,
                                          __nv_bfloat16* Bh, __nv_bfloat16* Bl) {
    const int tid = threadIdx.x;
#pragma unroll
    for (int i = 0; i < 4; i++) {
        const int idx = tid + i * 256;          // 1024 float4 total
        const int r = idx >> 5;
        const int c = (idx & 31) * 4;
        float4 v = *reinterpret_cast<const float4*>(g + (size_t)r * ld + c);
        __nv_bfloat16* ph = Bh + r * LDBT + c;
        __nv_bfloat16* pl = Bl + r * LDBT + c;
        split2(v.x, ph[0], pl[0]);
        split2(v.y, ph[1], pl[1]);
        split2(v.z, ph[2], pl[2]);
        split2(v.w, ph[3], pl[3]);
    }
}

// bf16 pair [128][32] tile -> copy into [128][40]
__device__ __forceinline__ void loadT_bf16(const __nv_bfloat16* gh, const __nv_bfloat16* gl,
                                           int ld, __nv_bfloat16* Th, __nv_bfloat16* Tl) {
    const int tid = threadIdx.x;
#pragma unroll
    for (int i = 0; i < 2; i++) {
        const int idx = tid + i * 256;          // 512 uint4 per array
        const int r = idx >> 2;
        const int c = (idx & 3) * 8;
        *reinterpret_cast<uint4*>(Th + r * LDA + c) =
            *reinterpret_cast<const uint4*>(gh + (size_t)r * ld + c);
        *reinterpret_cast<uint4*>(Tl + r * LDA + c) =
            *reinterpret_cast<const uint4*>(gl + (size_t)r * ld + c);
    }
}

// bf16 pair [32][128] V tile -> copy into [32][136]
__device__ __forceinline__ void loadV_bf16(const __nv_bfloat16* gh, const __nv_bfloat16* gl,
                                           int ld, __nv_bfloat16* Bh, __nv_bfloat16* Bl) {
    const int tid = threadIdx.x;
#pragma unroll
    for (int i = 0; i < 2; i++) {
        const int idx = tid + i * 256;          // 512 uint4 per array
        const int r = idx >> 4;
        const int c = (idx & 15) * 8;
        *reinterpret_cast<uint4*>(Bh + r * LDBT + c) =
            *reinterpret_cast<const uint4*>(gh + (size_t)r * ld + c);
        *reinterpret_cast<uint4*>(Bl + r * LDBT + c) =
            *reinterpret_cast<const uint4*>(gl + (size_t)r * ld + c);
    }
}

// ---------------------------------------------------------------------------
// Kernel 1: Q/K/V projection.  C = x @ W + b, split-stored.
// grid (N/128=8, M/128=64, 3), block 256.
// ---------------------------------------------------------------------------
__global__ void __launch_bounds__(256) qkv_kernel(
    const float* __restrict__ x,
    const float* __restrict__ Wq, const float* __restrict__ bq,
    const float* __restrict__ Wk, const float* __restrict__ bk,
    const float* __restrict__ Wv, const float* __restrict__ bv) {
    __shared__ __nv_bfloat16 Ah[128 * LDA], Al[128 * LDA];
    __shared__ __nv_bfloat16 Bh[32 * LDBT], Bl[32 * LDBT];

    const int m0 = blockIdx.y * 128;
    const int n0 = blockIdx.x * 128;

    const float* W; const float* bias;
    __nv_bfloat16 *oh, *ol;
    if (blockIdx.z == 0)      { W = Wq; bias = bq; oh = g_Qh; ol = g_Ql; }
    else if (blockIdx.z == 1) { W = Wk; bias = bk; oh = g_Kh; ol = g_Kl; }
    else                      { W = Wv; bias = bv; oh = g_Vh; ol = g_Vl; }

    float acc[4][4][4] = {};

    for (int k0 = 0; k0 < DIM; k0 += 32) {
        loadA_f32(x + (size_t)m0 * DIM + k0, DIM, Ah, Al);
        loadB_f32(W + (size_t)k0 * DIM + n0, DIM, Bh, Bl);
        __syncthreads();
        mma_tile<LDBT, true>(Ah, Al, Bh, Bl, acc);
        __syncthreads();
    }

    const int lane = threadIdx.x & 31, warp = threadIdx.x >> 5;
    const int wm = (warp >> 2) * 64, wn = (warp & 3) * 32;
#pragma unroll
    for (int mt = 0; mt < 4; mt++)
#pragma unroll
        for (int nt = 0; nt < 4; nt++) {
            const int col = n0 + wn + nt * 8 + (lane & 3) * 2;
#pragma unroll
            for (int h = 0; h < 2; h++) {
                const int row = m0 + wm + mt * 16 + (lane >> 2) + h * 8;
                const float v0 = acc[mt][nt][2 * h + 0] + bias[col];
                const float v1 = acc[mt][nt][2 * h + 1] + bias[col + 1];
                const size_t o = (size_t)row * DIM + col;
                split2(v0, oh[o], ol[o]);
                split2(v1, oh[o + 1], ol[o + 1]);
            }
        }
}

// ---------------------------------------------------------------------------
// Kernel 2: scores = Q @ K^T * scale (per batch).  grid (16, 16, 4).
// ---------------------------------------------------------------------------
__global__ void __launch_bounds__(256) scores_kernel() {
    __shared__ __nv_bfloat16 Ah[128 * LDA], Al[128 * LDA];
    __shared__ __nv_bfloat16 Bh[128 * LDA], Bl[128 * LDA];

    const int z = blockIdx.z;
    const int m0 = blockIdx.y * 128;
    const int n0 = blockIdx.x * 128;
    const size_t base = (size_t)z * SEQ * DIM;

    float acc[4][4][4] = {};

    for (int k0 = 0; k0 < DIM; k0 += 32) {
        loadT_bf16(g_Qh + base + (size_t)m0 * DIM + k0,
                   g_Ql + base + (size_t)m0 * DIM + k0, DIM, Ah, Al);
        loadT_bf16(g_Kh + base + (size_t)n0 * DIM + k0,
                   g_Kl + base + (size_t)n0 * DIM + k0, DIM, Bh, Bl);
        __syncthreads();
        mma_tile<LDA, false>(Ah, Al, Bh, Bl, acc);
        __syncthreads();
    }

    const float scale = 0.03125f;   // 1/sqrt(1024)
    float* Sc = g_Sc + (size_t)z * SEQ * SEQ;
    const int lane = threadIdx.x & 31, warp = threadIdx.x >> 5;
    const int wm = (warp >> 2) * 64, wn = (warp & 3) * 32;
#pragma unroll
    for (int mt = 0; mt < 4; mt++)
#pragma unroll
        for (int nt = 0; nt < 4; nt++) {
            const int col = n0 + wn + nt * 8 + (lane & 3) * 2;
#pragma unroll
            for (int h = 0; h < 2; h++) {
                const int row = m0 + wm + mt * 16 + (lane >> 2) + h * 8;
                Sc[(size_t)row * SEQ + col]     = acc[mt][nt][2 * h + 0] * scale;
                Sc[(size_t)row * SEQ + col + 1] = acc[mt][nt][2 * h + 1] * scale;
            }
        }
}

// ---------------------------------------------------------------------------
// Kernel 3: row softmax over g_Sc (8192 rows x 2048), in place.
// ---------------------------------------------------------------------------
__global__ void __launch_bounds__(256) softmax_kernel() {
    float* row = g_Sc + (size_t)blockIdx.x * SEQ;
    const int tid = threadIdx.x;

    float4 v0 = *reinterpret_cast<const float4*>(row + tid * 4);
    float4 v1 = *reinterpret_cast<const float4*>(row + 1024 + tid * 4);

    __shared__ float red[8];

    float m = fmaxf(fmaxf(fmaxf(v0.x, v0.y), fmaxf(v0.z, v0.w)),
                    fmaxf(fmaxf(v1.x, v1.y), fmaxf(v1.z, v1.w)));
#pragma unroll
    for (int o = 16; o > 0; o >>= 1) m = fmaxf(m, __shfl_xor_sync(0xffffffffu, m, o));
    if ((tid & 31) == 0) red[tid >> 5] = m;
    __syncthreads();
    m = red[0];
#pragma unroll
    for (int i = 1; i < 8; i++) m = fmaxf(m, red[i]);
    __syncthreads();

    v0.x = expf(v0.x - m); v0.y = expf(v0.y - m);
    v0.z = expf(v0.z - m); v0.w = expf(v0.w - m);
    v1.x = expf(v1.x - m); v1.y = expf(v1.y - m);
    v1.z = expf(v1.z - m); v1.w = expf(v1.w - m);

    float s = (v0.x + v0.y) + (v0.z + v0.w) + (v1.x + v1.y) + (v1.z + v1.w);
#pragma unroll
    for (int o = 16; o > 0; o >>= 1) s += __shfl_xor_sync(0xffffffffu, s, o);
    if ((tid & 31) == 0) red[tid >> 5] = s;
    __syncthreads();
    s = red[0];
#pragma unroll
    for (int i = 1; i < 8; i++) s += red[i];

    const float inv = 1.0f / s;
    v0.x *= inv; v0.y *= inv; v0.z *= inv; v0.w *= inv;
    v1.x *= inv; v1.y *= inv; v1.z *= inv; v1.w *= inv;

    *reinterpret_cast<float4*>(row + tid * 4) = v0;
    *reinterpret_cast<float4*>(row + 1024 + tid * 4) = v1;
}

// ---------------------------------------------------------------------------
// Kernel 4: out = P @ V (per batch).  grid (8, 16, 4).
// ---------------------------------------------------------------------------
__global__ void __launch_bounds__(256) pv_kernel(float* __restrict__ out) {
    __shared__ __nv_bfloat16 Ah[128 * LDA], Al[128 * LDA];
    __shared__ __nv_bfloat16 Bh[32 * LDBT], Bl[32 * LDBT];

    const int z = blockIdx.z;
    const int m0 = blockIdx.y * 128;
    const int n0 = blockIdx.x * 128;
    const float* P = g_Sc + (size_t)z * SEQ * SEQ;
    const size_t vbase = (size_t)z * SEQ * DIM;

    float acc[4][4][4] = {};

    for (int k0 = 0; k0 < SEQ; k0 += 32) {
        loadA_f32(P + (size_t)m0 * SEQ + k0, SEQ, Ah, Al);
        loadV_bf16(g_Vh + vbase + (size_t)k0 * DIM + n0,
                   g_Vl + vbase + (size_t)k0 * DIM + n0, DIM, Bh, Bl);
        __syncthreads();
        mma_tile<LDBT, true>(Ah, Al, Bh, Bl, acc);
        __syncthreads();
    }

    const int lane = threadIdx.x & 31, warp = threadIdx.x >> 5;
    const int wm = (warp >> 2) * 64, wn = (warp & 3) * 32;
#pragma unroll
    for (int mt = 0; mt < 4; mt++)
#pragma unroll
        for (int nt = 0; nt < 4; nt++) {
            const int col = n0 + wn + nt * 8 + (lane & 3) * 2;
#pragma unroll
            for (int h = 0; h < 2; h++) {
                const int row = m0 + wm + mt * 16 + (lane >> 2) + h * 8;
                const size_t o = ((size_t)z * SEQ + row) * DIM + col;
                out[o]     = acc[mt][nt][2 * h + 0];
                out[o + 1] = acc[mt][nt][2 * h + 1];
            }
        }
}

// ---------------------------------------------------------------------------
// kernel_launch: x, Wq, bq, Wk, bk, Wv, bv  ->  out [4,2048,1024] fp32
// ---------------------------------------------------------------------------
extern "C" void kernel_launch(void* const* d_in, const int* in_sizes, int n_in,
                              void* d_out, int out_size) {
    (void)in_sizes; (void)n_in; (void)out_size;
    const float* x  = (const float*)d_in[0];
    const float* Wq = (const float*)d_in[1];
    const float* bq = (const float*)d_in[2];
    const float* Wk = (const float*)d_in[3];
    const float* bk = (const float*)d_in[4];
    const float* Wv = (const float*)d_in[5];
    const float* bv = (const float*)d_in[6];
    float* out = (float*)d_out;

    qkv_kernel<<<dim3(DIM / 128, MTOT / 128, 3), 256>>>(x, Wq, bq, Wk, bk, Wv, bv);
    scores_kernel<<<dim3(SEQ / 128, SEQ / 128, BATCH), 256>>>();
    softmax_kernel<<<MTOT, 256>>>();
    pv_kernel<<<dim3(DIM / 128, SEQ / 128, BATCH), 256>>>(out);
}

// round 5
// speedup vs baseline: 1.0004x; 1.0004x over previous
#include <cuda_runtime.h>
#include <cuda_bf16.h>
#include <cstdint>

// Problem sizes (fixed by the reference)
#define BATCH 4
#define SEQ   2048
#define DIM   1024
#define MTOT  (BATCH * SEQ)   // 8192

// ---------------------------------------------------------------------------
// Scratch (static __device__ arrays — no allocation allowed)
// Q/K/V stored as split bf16 (hi + lo) so downstream GEMMs read tensor-core-
// ready operands. Scores/probs in fp32.
// ---------------------------------------------------------------------------
__device__ __nv_bfloat16 g_Qh[(size_t)MTOT * DIM];
__device__ __nv_bfloat16 g_Ql[(size_t)MTOT * DIM];
__device__ __nv_bfloat16 g_Kh[(size_t)MTOT * DIM];
__device__ __nv_bfloat16 g_Kl[(size_t)MTOT * DIM];
__device__ __nv_bfloat16 g_Vh[(size_t)MTOT * DIM];
__device__ __nv_bfloat16 g_Vl[(size_t)MTOT * DIM];
__device__ float         g_Sc[(size_t)BATCH * SEQ * SEQ];   // 64 MB

// ---------------------------------------------------------------------------
// PTX helpers
// ---------------------------------------------------------------------------
__device__ __forceinline__ uint32_t smem_u32(const void* p) {
    return (uint32_t)__cvta_generic_to_shared(p);
}

__device__ __forceinline__ void ldsm4(uint32_t addr, uint32_t& r0, uint32_t& r1,
                                      uint32_t& r2, uint32_t& r3) {
    asm volatile("ldmatrix.sync.aligned.m8n8.x4.shared.b16 {%0,%1,%2,%3},[%4];"
                 : "=r"(r0), "=r"(r1), "=r"(r2), "=r"(r3) : "r"(addr));
}

__device__ __forceinline__ void ldsm4t(uint32_t addr, uint32_t& r0, uint32_t& r1,
                                       uint32_t& r2, uint32_t& r3) {
    asm volatile("ldmatrix.sync.aligned.m8n8.x4.trans.shared.b16 {%0,%1,%2,%3},[%4];"
                 : "=r"(r0), "=r"(r1), "=r"(r2), "=r"(r3) : "r"(addr));
}

__device__ __forceinline__ void mma16816(float* c, const uint32_t* a, const uint32_t* b) {
    asm volatile(
        "mma.sync.aligned.m16n8k16.row.col.f32.bf16.bf16.f32 "
        "{%0,%1,%2,%3},{%4,%5,%6,%7},{%8,%9},{%0,%1,%2,%3};"
        : "+f"(c[0]), "+f"(c[1]), "+f"(c[2]), "+f"(c[3])
        : "r"(a[0]), "r"(a[1]), "r"(a[2]), "r"(a[3]), "r"(b[0]), "r"(b[1]));
}

__device__ __forceinline__ void split2(float x, __nv_bfloat16& h, __nv_bfloat16& l) {
    h = __float2bfloat16(x);                            // rn
    l = __float2bfloat16(x - __bfloat162float(h));      // residual, exact subtract
}

// ---------------------------------------------------------------------------
// Shared-memory tile layouts:
//   A tiles:   [128][40] bf16  (BK=32 + pad 8; 80B row stride, 16B aligned,
//                               ldmatrix bank-conflict free)
//   B (n,k):   [128][40] bf16  (scores kernel: K rows are k-contiguous)
//   B (k,n):   [32][136] bf16  (weights / V: n-contiguous rows, trans ldmatrix)
// ---------------------------------------------------------------------------
#define LDA  40
#define LDBT 136

// Core 128x128x32 split-bf16 MMA step. 8 warps as 2(m) x 4(n); each warp owns
// 64x32 of C: 4 m16 tiles x 4 n8 tiles, 3 split combos -> 48 mma per BK=32.
template <int LDB, bool BTRANS>
__device__ __forceinline__ void mma_tile(const __nv_bfloat16* Ah, const __nv_bfloat16* Al,
                                         const __nv_bfloat16* Bh, const __nv_bfloat16* Bl,
                                         float acc[4][4][4]) {
    const int lane = threadIdx.x & 31;
    const int warp = threadIdx.x >> 5;
    const int wm = (warp >> 2) * 64;
    const int wn = (warp & 3) * 32;

#pragma unroll
    for (int ks = 0; ks < 32; ks += 16) {
        uint32_t ah[4][4], al[4][4];
#pragma unroll
        for (int mt = 0; mt < 4; mt++) {
            const int row = wm + mt * 16 + (lane & 15);
            const int col = ks + ((lane >> 4) << 3);
            ldsm4(smem_u32(Ah + row * LDA + col), ah[mt][0], ah[mt][1], ah[mt][2], ah[mt][3]);
            ldsm4(smem_u32(Al + row * LDA + col), al[mt][0], al[mt][1], al[mt][2], al[mt][3]);
        }
        uint32_t bh[4][2], bl[4][2];
#pragma unroll
        for (int np = 0; np < 2; np++) {
            const int nb = wn + np * 16;
            uint32_t r0, r1, r2, r3;
            if (BTRANS) {
                const int grp  = lane >> 3;
                const int krow = ks + ((grp & 1) << 3) + (lane & 7);
                const int ncol = nb + ((grp & 2) << 2);
                ldsm4t(smem_u32(Bh + krow * LDB + ncol), r0, r1, r2, r3);
                bh[2 * np][0] = r0; bh[2 * np][1] = r1;
                bh[2 * np + 1][0] = r2; bh[2 * np + 1][1] = r3;
                ldsm4t(smem_u32(Bl + krow * LDB + ncol), r0, r1, r2, r3);
                bl[2 * np][0] = r0; bl[2 * np][1] = r1;
                bl[2 * np + 1][0] = r2; bl[2 * np + 1][1] = r3;
            } else {
                const int grp  = lane >> 3;
                const int nrow = nb + ((grp & 2) << 2) + (lane & 7);
                const int kcol = ks + ((grp & 1) << 3);
                ldsm4(smem_u32(Bh + nrow * LDB + kcol), r0, r1, r2, r3);
                bh[2 * np][0] = r0; bh[2 * np][1] = r1;
                bh[2 * np + 1][0] = r2; bh[2 * np + 1][1] = r3;
                ldsm4(smem_u32(Bl + nrow * LDB + kcol), r0, r1, r2, r3);
                bl[2 * np][0] = r0; bl[2 * np][1] = r1;
                bl[2 * np + 1][0] = r2; bl[2 * np + 1][1] = r3;
            }
        }
#pragma unroll
        for (int mt = 0; mt < 4; mt++)
#pragma unroll
            for (int nt = 0; nt < 4; nt++) {
                mma16816(acc[mt][nt], ah[mt], bh[nt]);   // hi*hi
                mma16816(acc[mt][nt], ah[mt], bl[nt]);   // hi*lo
                mma16816(acc[mt][nt], al[mt], bh[nt]);   // lo*hi
            }
    }
}

// ---- tile loaders ---------------------------------------------------------

// fp32 [128][32] tile -> split hi/lo into [128][40]
__device__ __forceinline__ void loadA_f32(const float* g, int ld,
                                          __nv_bfloat16* Ah, __nv_bfloat16* Al) {
    const int tid = threadIdx.x;
#pragma unroll
    for (int i = 0; i < 4; i++) {
        const int idx = tid + i * 256;          // 1024 float4 total
        const int r = idx >> 3;
        const int c = (idx & 7) * 4;
        float4 v = *reinterpret_cast<const float4*>(g + (size_t)r * ld + c);
        __nv_bfloat16* ph = Ah + r * LDA + c;
        __nv_bfloat16* pl = Al + r * LDA + c;
        split2(v.x, ph[0], pl[0]);
        split2(v.y, ph[1], pl[1]);
        split2(v.z, ph[2], pl[2]);
        split2(v.w, ph[3], pl[3]);
    }
}

// fp32 [32][128] weight tile -> split hi/lo into [32][136]
__device__ __forceinline__ void loadB_f32(const float* g, int ld,
                                          __nv_bfloat16* Bh, __nv_bfloat16* Bl) {
    const int tid = threadIdx.x;
#pragma unroll
    for (int i = 0; i < 4; i++) {
        const int idx = tid + i * 256;          // 1024 float4 total
        const int r = idx >> 5;
        const int c = (idx & 31) * 4;
        float4 v = *reinterpret_cast<const float4*>(g + (size_t)r * ld + c);
        __nv_bfloat16* ph = Bh + r * LDBT + c;
        __nv_bfloat16* pl = Bl + r * LDBT + c;
        split2(v.x, ph[0], pl[0]);
        split2(v.y, ph[1], pl[1]);
        split2(v.z, ph[2], pl[2]);
        split2(v.w, ph[3], pl[3]);
    }
}

// bf16 pair [128][32] tile -> copy into [128][40]
__device__ __forceinline__ void loadT_bf16(const __nv_bfloat16* gh, const __nv_bfloat16* gl,
                                           int ld, __nv_bfloat16* Th, __nv_bfloat16* Tl) {
    const int tid = threadIdx.x;
#pragma unroll
    for (int i = 0; i < 2; i++) {
        const int idx = tid + i * 256;          // 512 uint4 per array
        const int r = idx >> 2;
        const int c = (idx & 3) * 8;
        *reinterpret_cast<uint4*>(Th + r * LDA + c) =
            *reinterpret_cast<const uint4*>(gh + (size_t)r * ld + c);
        *reinterpret_cast<uint4*>(Tl + r * LDA + c) =
            *reinterpret_cast<const uint4*>(gl + (size_t)r * ld + c);
    }
}

// bf16 pair [32][128] V tile -> copy into [32][136]
__device__ __forceinline__ void loadV_bf16(const __nv_bfloat16* gh, const __nv_bfloat16* gl,
                                           int ld, __nv_bfloat16* Bh, __nv_bfloat16* Bl) {
    const int tid = threadIdx.x;
#pragma unroll
    for (int i = 0; i < 2; i++) {
        const int idx = tid + i * 256;          // 512 uint4 per array
        const int r = idx >> 4;
        const int c = (idx & 15) * 8;
        *reinterpret_cast<uint4*>(Bh + r * LDBT + c) =
            *reinterpret_cast<const uint4*>(gh + (size_t)r * ld + c);
        *reinterpret_cast<uint4*>(Bl + r * LDBT + c) =
            *reinterpret_cast<const uint4*>(gl + (size_t)r * ld + c);
    }
}

// ---------------------------------------------------------------------------
// Kernel 1: Q/K/V projection.  C = x @ W + b, split-stored.
// grid (N/128=8, M/128=64, 3), block 256.
// ---------------------------------------------------------------------------
__global__ void __launch_bounds__(256) qkv_kernel(
    const float* __restrict__ x,
    const float* __restrict__ Wq, const float* __restrict__ bq,
    const float* __restrict__ Wk, const float* __restrict__ bk,
    const float* __restrict__ Wv, const float* __restrict__ bv) {
    __shared__ __nv_bfloat16 Ah[128 * LDA], Al[128 * LDA];
    __shared__ __nv_bfloat16 Bh[32 * LDBT], Bl[32 * LDBT];

    const int m0 = blockIdx.y * 128;
    const int n0 = blockIdx.x * 128;

    const float* W; const float* bias;
    __nv_bfloat16 *oh, *ol;
    if (blockIdx.z == 0)      { W = Wq; bias = bq; oh = g_Qh; ol = g_Ql; }
    else if (blockIdx.z == 1) { W = Wk; bias = bk; oh = g_Kh; ol = g_Kl; }
    else                      { W = Wv; bias = bv; oh = g_Vh; ol = g_Vl; }

    float acc[4][4][4] = {};

    for (int k0 = 0; k0 < DIM; k0 += 32) {
        loadA_f32(x + (size_t)m0 * DIM + k0, DIM, Ah, Al);
        loadB_f32(W + (size_t)k0 * DIM + n0, DIM, Bh, Bl);
        __syncthreads();
        mma_tile<LDBT, true>(Ah, Al, Bh, Bl, acc);
        __syncthreads();
    }

    const int lane = threadIdx.x & 31, warp = threadIdx.x >> 5;
    const int wm = (warp >> 2) * 64, wn = (warp & 3) * 32;
#pragma unroll
    for (int mt = 0; mt < 4; mt++)
#pragma unroll
        for (int nt = 0; nt < 4; nt++) {
            const int col = n0 + wn + nt * 8 + (lane & 3) * 2;
#pragma unroll
            for (int h = 0; h < 2; h++) {
                const int row = m0 + wm + mt * 16 + (lane >> 2) + h * 8;
                const float v0 = acc[mt][nt][2 * h + 0] + bias[col];
                const float v1 = acc[mt][nt][2 * h + 1] + bias[col + 1];
                const size_t o = (size_t)row * DIM + col;
                split2(v0, oh[o], ol[o]);
                split2(v1, oh[o + 1], ol[o + 1]);
            }
        }
}

// ---------------------------------------------------------------------------
// Kernel 2: scores = Q @ K^T * scale (per batch).  grid (16, 16, 4).
// ---------------------------------------------------------------------------
__global__ void __launch_bounds__(256) scores_kernel() {
    __shared__ __nv_bfloat16 Ah[128 * LDA], Al[128 * LDA];
    __shared__ __nv_bfloat16 Bh[128 * LDA], Bl[128 * LDA];

    const int z = blockIdx.z;
    const int m0 = blockIdx.y * 128;
    const int n0 = blockIdx.x * 128;
    const size_t base = (size_t)z * SEQ * DIM;

    float acc[4][4][4] = {};

    for (int k0 = 0; k0 < DIM; k0 += 32) {
        loadT_bf16(g_Qh + base + (size_t)m0 * DIM + k0,
                   g_Ql + base + (size_t)m0 * DIM + k0, DIM, Ah, Al);
        loadT_bf16(g_Kh + base + (size_t)n0 * DIM + k0,
                   g_Kl + base + (size_t)n0 * DIM + k0, DIM, Bh, Bl);
        __syncthreads();
        mma_tile<LDA, false>(Ah, Al, Bh, Bl, acc);
        __syncthreads();
    }

    const float scale = 0.03125f;   // 1/sqrt(1024)
    float* Sc = g_Sc + (size_t)z * SEQ * SEQ;
    const int lane = threadIdx.x & 31, warp = threadIdx.x >> 5;
    const int wm = (warp >> 2) * 64, wn = (warp & 3) * 32;
#pragma unroll
    for (int mt = 0; mt < 4; mt++)
#pragma unroll
        for (int nt = 0; nt < 4; nt++) {
            const int col = n0 + wn + nt * 8 + (lane & 3) * 2;
#pragma unroll
            for (int h = 0; h < 2; h++) {
                const int row = m0 + wm + mt * 16 + (lane >> 2) + h * 8;
                Sc[(size_t)row * SEQ + col]     = acc[mt][nt][2 * h + 0] * scale;
                Sc[(size_t)row * SEQ + col + 1] = acc[mt][nt][2 * h + 1] * scale;
            }
        }
}

// ---------------------------------------------------------------------------
// Kernel 3: row softmax over g_Sc (8192 rows x 2048), in place.
// ---------------------------------------------------------------------------
__global__ void __launch_bounds__(256) softmax_kernel() {
    float* row = g_Sc + (size_t)blockIdx.x * SEQ;
    const int tid = threadIdx.x;

    float4 v0 = *reinterpret_cast<const float4*>(row + tid * 4);
    float4 v1 = *reinterpret_cast<const float4*>(row + 1024 + tid * 4);

    __shared__ float red[8];

    float m = fmaxf(fmaxf(fmaxf(v0.x, v0.y), fmaxf(v0.z, v0.w)),
                    fmaxf(fmaxf(v1.x, v1.y), fmaxf(v1.z, v1.w)));
#pragma unroll
    for (int o = 16; o > 0; o >>= 1) m = fmaxf(m, __shfl_xor_sync(0xffffffffu, m, o));
    if ((tid & 31) == 0) red[tid >> 5] = m;
    __syncthreads();
    m = red[0];
#pragma unroll
    for (int i = 1; i < 8; i++) m = fmaxf(m, red[i]);
    __syncthreads();

    v0.x = expf(v0.x - m); v0.y = expf(v0.y - m);
    v0.z = expf(v0.z - m); v0.w = expf(v0.w - m);
    v1.x = expf(v1.x - m); v1.y = expf(v1.y - m);
    v1.z = expf(v1.z - m); v1.w = expf(v1.w - m);

    float s = (v0.x + v0.y) + (v0.z + v0.w) + (v1.x + v1.y) + (v1.z + v1.w);
#pragma unroll
    for (int o = 16; o > 0; o >>= 1) s += __shfl_xor_sync(0xffffffffu, s, o);
    if ((tid & 31) == 0) red[tid >> 5] = s;
    __syncthreads();
    s = red[0];
#pragma unroll
    for (int i = 1; i < 8; i++) s += red[i];

    const float inv = 1.0f / s;
    v0.x *= inv; v0.y *= inv; v0.z *= inv; v0.w *= inv;
    v1.x *= inv; v1.y *= inv; v1.z *= inv; v1.w *= inv;

    *reinterpret_cast<float4*>(row + tid * 4) = v0;
    *reinterpret_cast<float4*>(row + 1024 + tid * 4) = v1;
}

// ---------------------------------------------------------------------------
// Kernel 4: out = P @ V (per batch).  grid (8, 16, 4).
// ---------------------------------------------------------------------------
__global__ void __launch_bounds__(256) pv_kernel(float* __restrict__ out) {
    __shared__ __nv_bfloat16 Ah[128 * LDA], Al[128 * LDA];
    __shared__ __nv_bfloat16 Bh[32 * LDBT], Bl[32 * LDBT];

    const int z = blockIdx.z;
    const int m0 = blockIdx.y * 128;
    const int n0 = blockIdx.x * 128;
    const float* P = g_Sc + (size_t)z * SEQ * SEQ;
    const size_t vbase = (size_t)z * SEQ * DIM;

    float acc[4][4][4] = {};

    for (int k0 = 0; k0 < SEQ; k0 += 32) {
        loadA_f32(P + (size_t)m0 * SEQ + k0, SEQ, Ah, Al);
        loadV_bf16(g_Vh + vbase + (size_t)k0 * DIM + n0,
                   g_Vl + vbase + (size_t)k0 * DIM + n0, DIM, Bh, Bl);
        __syncthreads();
        mma_tile<LDBT, true>(Ah, Al, Bh, Bl, acc);
        __syncthreads();
    }

    const int lane = threadIdx.x & 31, warp = threadIdx.x >> 5;
    const int wm = (warp >> 2) * 64, wn = (warp & 3) * 32;
#pragma unroll
    for (int mt = 0; mt < 4; mt++)
#pragma unroll
        for (int nt = 0; nt < 4; nt++) {
            const int col = n0 + wn + nt * 8 + (lane & 3) * 2;
#pragma unroll
            for (int h = 0; h < 2; h++) {
                const int row = m0 + wm + mt * 16 + (lane >> 2) + h * 8;
                const size_t o = ((size_t)z * SEQ + row) * DIM + col;
                out[o]     = acc[mt][nt][2 * h + 0];
                out[o + 1] = acc[mt][nt][2 * h + 1];
            }
        }
}

// ---------------------------------------------------------------------------
// kernel_launch: x, Wq, bq, Wk, bk, Wv, bv  ->  out [4,2048,1024] fp32
// ---------------------------------------------------------------------------
extern "C" void kernel_launch(void* const* d_in, const int* in_sizes, int n_in,
                              void* d_out, int out_size) {
    (void)in_sizes; (void)n_in; (void)out_size;
    const float* x  = (const float*)d_in[0];
    const float* Wq = (const float*)d_in[1];
    const float* bq = (const float*)d_in[2];
    const float* Wk = (const float*)d_in[3];
    const float* bk = (const float*)d_in[4];
    const float* Wv = (const float*)d_in[5];
    const float* bv = (const float*)d_in[6];
    float* out = (float*)d_out;

    qkv_kernel<<<dim3(DIM / 128, MTOT / 128, 3), 256>>>(x, Wq, bq, Wk, bk, Wv, bv);
    scores_kernel<<<dim3(SEQ / 128, SEQ / 128, BATCH), 256>>>();
    softmax_kernel<<<MTOT, 256>>>();
    pv_kernel<<<dim3(DIM / 128, SEQ / 128, BATCH), 256>>>(out);
}